// round 14
// baseline (speedup 1.0000x reference)
#include <cuda_runtime.h>
#include <math.h>

// Problem constants (fixed by the reference's setup)
#define N_IN 1000000
#define M_NODES 2000000
#define S0 (2 * N_IN + 2)

// Scratch (no cudaMalloc allowed): encoded input + two ping-pong M-buffers
__device__ float g_enc[S0];
__device__ float g_bufA[M_NODES];
__device__ float g_bufB[M_NODES];

// log(1 - exp(x)) for x <= 0, stable (Maechler 2012), matching reference
__device__ __forceinline__ float log1mexp_f(float x) {
    const float NLOG2 = -0.69314718056f;
    if (x > NLOG2) {
        return logf(-expm1f(x));     // x in (-log2, 0]; x=0 -> log(0) = -inf
    } else {
        return log1pf(-expf(x));
    }
}

__global__ void __launch_bounds__(512) encode_kernel(const float* __restrict__ pos) {
    cudaTriggerProgrammaticLaunchCompletion();   // let product1 launch early
    int i = blockIdx.x * blockDim.x + threadIdx.x;
    if (i == 0) {
        g_enc[0] = -INFINITY;  // literal False
        g_enc[1] = 0.0f;       // literal True
    }
    if (i < N_IN) {
        float p = pos[i];
        g_enc[2 + 2 * i] = p;
        g_enc[3 + 2 * i] = log1mexp_f(p);
    }
}

// Gather with L1-bypass: random 4B gathers have ~3% L1 hit rate; skip the fill.
__device__ __forceinline__ float gcg(const float* p) { return __ldcg(p); }

// product layer: out[m] = sum of 4 gathered log-probs.
// Two-wave grid-stride + 2-stage ptr pipeline + PDL: the first ptr load
// (independent of the predecessor's output) is issued BEFORE
// cudaGridDependencySynchronize(), overlapping the predecessor's tail.
__global__ void __launch_bounds__(512) product_kernel(
        const float* __restrict__ src,
        const int4* __restrict__ ptrs,
        float* __restrict__ dst) {
    cudaTriggerProgrammaticLaunchCompletion();   // let successor launch early
    const int stride = gridDim.x * blockDim.x;
    int m = blockIdx.x * blockDim.x + threadIdx.x;
    if (m >= M_NODES) { cudaGridDependencySynchronize(); return; }
    int4 p = __ldcs(ptrs + m);                   // ptr stream: no dependency
    cudaGridDependencySynchronize();             // wait for predecessor data
    while (true) {
        int mn = m + stride;
        int4 pn;
        if (mn < M_NODES) pn = __ldcs(ptrs + mn);   // prefetch next ptrs
        float a = gcg(src + p.x);
        float b = gcg(src + p.y);
        float c = gcg(src + p.z);
        float d = gcg(src + p.w);
        __stcg(dst + m, (a + b) + (c + d));
        if (mn >= M_NODES) break;
        m = mn; p = pn;
    }
}

// sum layer: 4-way logsumexp with 1e-15 floor, max detached. Same structure.
__global__ void __launch_bounds__(512) sum_kernel(
        const float* __restrict__ src,
        const int4* __restrict__ ptrs,
        float* __restrict__ dst) {
    cudaTriggerProgrammaticLaunchCompletion();
    const int stride = gridDim.x * blockDim.x;
    int m = blockIdx.x * blockDim.x + threadIdx.x;
    if (m >= M_NODES) { cudaGridDependencySynchronize(); return; }
    int4 p = __ldcs(ptrs + m);
    cudaGridDependencySynchronize();
    while (true) {
        int mn = m + stride;
        int4 pn;
        if (mn < M_NODES) pn = __ldcs(ptrs + mn);
        float a = gcg(src + p.x);
        float b = gcg(src + p.y);
        float c = gcg(src + p.z);
        float d = gcg(src + p.w);
        float mx = fmaxf(fmaxf(a, b), fmaxf(c, d));
        float out;
        if (mx == -INFINITY) {
            out = -INFINITY;            // reference nan_to_num path
        } else {
            float s = __expf(a - mx) + __expf(b - mx)
                    + __expf(c - mx) + __expf(d - mx);
            out = __logf(s + 1e-15f) + mx;
        }
        __stcg(dst + m, out);
        if (mn >= M_NODES) break;
        m = mn; p = pn;
    }
}

// Launch helper: secondary kernels use programmatic stream serialization so
// they may begin (and stream their ptr arrays) before the predecessor ends.
template <typename... Args>
static void launch_pdl(void (*kernel)(Args...), dim3 grid, dim3 block,
                       Args... args) {
    cudaLaunchConfig_t cfg = {};
    cfg.gridDim = grid;
    cfg.blockDim = block;
    cudaLaunchAttribute attr[1];
    attr[0].id = cudaLaunchAttributeProgrammaticStreamSerialization;
    attr[0].val.programmaticStreamSerializationAllowed = 1;
    cfg.attrs = attr;
    cfg.numAttrs = 1;
    cudaLaunchKernelEx(&cfg, kernel, args...);
}

extern "C" void kernel_launch(void* const* d_in, const int* in_sizes, int n_in,
                              void* d_out, int out_size) {
    const float* pos   = (const float*)d_in[0];
    const int4*  ptrs0 = (const int4*)d_in[1];
    const int4*  ptrs1 = (const int4*)d_in[2];
    const int4*  ptrs2 = (const int4*)d_in[3];
    const int4*  ptrs3 = (const int4*)d_in[4];
    // d_in[5] (csr = repeat(arange(M),4)) is implicit in the layout.
    float* out = (float*)d_out;

    float* enc;  cudaGetSymbolAddress((void**)&enc,  g_enc);
    float* bufA; cudaGetSymbolAddress((void**)&bufA, g_bufA);
    float* bufB; cudaGetSymbolAddress((void**)&bufB, g_bufB);

    const int T = 512;
    const int blocksEnc = (N_IN + T - 1) / T;
    const int blocksM   = 148 * 8;   // two waves of 4-resident blocks/SM

    encode_kernel<<<blocksEnc, T>>>(pos);
    launch_pdl(product_kernel, dim3(blocksM), dim3(T),
               (const float*)enc,  ptrs0, bufA);
    launch_pdl(sum_kernel,     dim3(blocksM), dim3(T),
               (const float*)bufA, ptrs1, bufB);
    launch_pdl(product_kernel, dim3(blocksM), dim3(T),
               (const float*)bufB, ptrs2, bufA);
    launch_pdl(sum_kernel,     dim3(blocksM), dim3(T),
               (const float*)bufA, ptrs3, out);
}

// round 15
// speedup vs baseline: 1.5620x; 1.5620x over previous
#include <cuda_runtime.h>
#include <math.h>

// Problem constants (fixed by the reference's setup)
#define N_IN 1000000
#define M_NODES 2000000
#define S0 (2 * N_IN + 2)

// Scratch (no cudaMalloc allowed): encoded input + two ping-pong M-buffers
__device__ float g_enc[S0];
__device__ float g_bufA[M_NODES];
__device__ float g_bufB[M_NODES];

// log(1 - exp(x)) for x <= 0, stable (Maechler 2012), matching reference
__device__ __forceinline__ float log1mexp_f(float x) {
    const float NLOG2 = -0.69314718056f;
    if (x > NLOG2) {
        return logf(-expm1f(x));     // x in (-log2, 0]; x=0 -> log(0) = -inf
    } else {
        return log1pf(-expf(x));
    }
}

__global__ void __launch_bounds__(512) encode_kernel(const float* __restrict__ pos) {
    int i = blockIdx.x * blockDim.x + threadIdx.x;
    if (i == 0) {
        g_enc[0] = -INFINITY;  // literal False
        g_enc[1] = 0.0f;       // literal True
    }
    if (i < N_IN) {
        float p = pos[i];
        g_enc[2 + 2 * i] = p;
        g_enc[3 + 2 * i] = log1mexp_f(p);
    }
}

// Gather with L1-bypass: random 4B gathers have ~3% L1 hit rate; skip the fill.
__device__ __forceinline__ float gcg(const float* p) { return __ldcg(p); }

// product layer: out[m] = sum of 4 gathered log-probs.
// Two-wave grid-stride with 2-stage ptr pipeline: next iteration's ptr int4
// is in DRAM flight while this iteration's gathers (L2) are serviced; the
// second wave of blocks restores retirement-driven SM load rebalancing.
// (Measured wave-axis: 1w=133.2, 2w=132.0 best, 3w=133.9; flat=133.6.
//  Falsified: ILP>1, L2 prefetch, PDL, per-kernel wave mixing.)
__global__ void __launch_bounds__(512) product_kernel(
        const float* __restrict__ src,
        const int4* __restrict__ ptrs,
        float* __restrict__ dst) {
    const int stride = gridDim.x * blockDim.x;
    int m = blockIdx.x * blockDim.x + threadIdx.x;
    if (m >= M_NODES) return;
    int4 p = __ldcs(ptrs + m);
    while (true) {
        int mn = m + stride;
        int4 pn;
        if (mn < M_NODES) pn = __ldcs(ptrs + mn);   // prefetch next ptrs
        float a = gcg(src + p.x);
        float b = gcg(src + p.y);
        float c = gcg(src + p.z);
        float d = gcg(src + p.w);
        __stcg(dst + m, (a + b) + (c + d));
        if (mn >= M_NODES) break;
        m = mn; p = pn;
    }
}

// sum layer: 4-way logsumexp with 1e-15 floor, max detached. Same pipeline.
__global__ void __launch_bounds__(512) sum_kernel(
        const float* __restrict__ src,
        const int4* __restrict__ ptrs,
        float* __restrict__ dst) {
    const int stride = gridDim.x * blockDim.x;
    int m = blockIdx.x * blockDim.x + threadIdx.x;
    if (m >= M_NODES) return;
    int4 p = __ldcs(ptrs + m);
    while (true) {
        int mn = m + stride;
        int4 pn;
        if (mn < M_NODES) pn = __ldcs(ptrs + mn);
        float a = gcg(src + p.x);
        float b = gcg(src + p.y);
        float c = gcg(src + p.z);
        float d = gcg(src + p.w);
        float mx = fmaxf(fmaxf(a, b), fmaxf(c, d));
        float out;
        if (mx == -INFINITY) {
            out = -INFINITY;            // reference nan_to_num path
        } else {
            float s = __expf(a - mx) + __expf(b - mx)
                    + __expf(c - mx) + __expf(d - mx);
            out = __logf(s + 1e-15f) + mx;
        }
        __stcg(dst + m, out);
        if (mn >= M_NODES) break;
        m = mn; p = pn;
    }
}

extern "C" void kernel_launch(void* const* d_in, const int* in_sizes, int n_in,
                              void* d_out, int out_size) {
    const float* pos   = (const float*)d_in[0];
    const int4*  ptrs0 = (const int4*)d_in[1];
    const int4*  ptrs1 = (const int4*)d_in[2];
    const int4*  ptrs2 = (const int4*)d_in[3];
    const int4*  ptrs3 = (const int4*)d_in[4];
    // d_in[5] (csr = repeat(arange(M),4)) is implicit in the layout.
    float* out = (float*)d_out;

    float* enc;  cudaGetSymbolAddress((void**)&enc,  g_enc);
    float* bufA; cudaGetSymbolAddress((void**)&bufA, g_bufA);
    float* bufB; cudaGetSymbolAddress((void**)&bufB, g_bufB);

    const int T = 512;
    const int blocksEnc = (N_IN + T - 1) / T;
    const int blocksM   = 148 * 8;   // two waves of 4-resident blocks/SM:
                                     // pipeline + retirement rebalancing

    encode_kernel <<<blocksEnc, T>>>(pos);
    product_kernel<<<blocksM, T>>>(enc,  ptrs0, bufA);
    sum_kernel    <<<blocksM, T>>>(bufA, ptrs1, bufB);
    product_kernel<<<blocksM, T>>>(bufB, ptrs2, bufA);
    sum_kernel    <<<blocksM, T>>>(bufA, ptrs3, out);
}

// round 16
// speedup vs baseline: 1.5657x; 1.0024x over previous
#include <cuda_runtime.h>
#include <math.h>

// Problem constants (fixed by the reference's setup)
#define N_IN 1000000
#define M_NODES 2000000
#define S0 (2 * N_IN + 2)

// Scratch (no cudaMalloc allowed): encoded input + two ping-pong M-buffers
__device__ float g_enc[S0];
__device__ float g_bufA[M_NODES];
__device__ float g_bufB[M_NODES];

// log(1 - exp(x)) for x <= 0, stable (Maechler 2012), matching reference
__device__ __forceinline__ float log1mexp_f(float x) {
    const float NLOG2 = -0.69314718056f;
    if (x > NLOG2) {
        return logf(-expm1f(x));     // x in (-log2, 0]; x=0 -> log(0) = -inf
    } else {
        return log1pf(-expf(x));
    }
}

__global__ void __launch_bounds__(256) encode_kernel(const float* __restrict__ pos) {
    int i = blockIdx.x * blockDim.x + threadIdx.x;
    if (i == 0) {
        g_enc[0] = -INFINITY;  // literal False
        g_enc[1] = 0.0f;       // literal True
    }
    if (i < N_IN) {
        float p = pos[i];
        g_enc[2 + 2 * i] = p;
        g_enc[3 + 2 * i] = log1mexp_f(p);
    }
}

// Gather with L1-bypass: random 4B gathers have ~3% L1 hit rate; skip the fill.
__device__ __forceinline__ float gcg(const float* p) { return __ldcg(p); }

// product layer: out[m] = sum of 4 gathered log-probs.
// Two-wave grid-stride with 2-stage ptr pipeline, 256-thr blocks: identical
// per-thread loop/stride as the 512-thr champion but 2x the block-retirement
// events per SM for finer load rebalancing.
__global__ void __launch_bounds__(256) product_kernel(
        const float* __restrict__ src,
        const int4* __restrict__ ptrs,
        float* __restrict__ dst) {
    const int stride = gridDim.x * blockDim.x;
    int m = blockIdx.x * blockDim.x + threadIdx.x;
    if (m >= M_NODES) return;
    int4 p = __ldcs(ptrs + m);
    while (true) {
        int mn = m + stride;
        int4 pn;
        if (mn < M_NODES) pn = __ldcs(ptrs + mn);   // prefetch next ptrs
        float a = gcg(src + p.x);
        float b = gcg(src + p.y);
        float c = gcg(src + p.z);
        float d = gcg(src + p.w);
        __stcg(dst + m, (a + b) + (c + d));
        if (mn >= M_NODES) break;
        m = mn; p = pn;
    }
}

// sum layer: 4-way logsumexp with 1e-15 floor, max detached. Same pipeline.
__global__ void __launch_bounds__(256) sum_kernel(
        const float* __restrict__ src,
        const int4* __restrict__ ptrs,
        float* __restrict__ dst) {
    const int stride = gridDim.x * blockDim.x;
    int m = blockIdx.x * blockDim.x + threadIdx.x;
    if (m >= M_NODES) return;
    int4 p = __ldcs(ptrs + m);
    while (true) {
        int mn = m + stride;
        int4 pn;
        if (mn < M_NODES) pn = __ldcs(ptrs + mn);
        float a = gcg(src + p.x);
        float b = gcg(src + p.y);
        float c = gcg(src + p.z);
        float d = gcg(src + p.w);
        float mx = fmaxf(fmaxf(a, b), fmaxf(c, d));
        float out;
        if (mx == -INFINITY) {
            out = -INFINITY;            // reference nan_to_num path
        } else {
            float s = __expf(a - mx) + __expf(b - mx)
                    + __expf(c - mx) + __expf(d - mx);
            out = __logf(s + 1e-15f) + mx;
        }
        __stcg(dst + m, out);
        if (mn >= M_NODES) break;
        m = mn; p = pn;
    }
}

extern "C" void kernel_launch(void* const* d_in, const int* in_sizes, int n_in,
                              void* d_out, int out_size) {
    const float* pos   = (const float*)d_in[0];
    const int4*  ptrs0 = (const int4*)d_in[1];
    const int4*  ptrs1 = (const int4*)d_in[2];
    const int4*  ptrs2 = (const int4*)d_in[3];
    const int4*  ptrs3 = (const int4*)d_in[4];
    // d_in[5] (csr = repeat(arange(M),4)) is implicit in the layout.
    float* out = (float*)d_out;

    float* enc;  cudaGetSymbolAddress((void**)&enc,  g_enc);
    float* bufA; cudaGetSymbolAddress((void**)&bufA, g_bufA);
    float* bufB; cudaGetSymbolAddress((void**)&bufB, g_bufB);

    const int T = 256;
    const int blocksEnc = (N_IN + T - 1) / T;
    const int blocksM   = 148 * 16;  // same threads/stride as 1184x512 champion;
                                     // 2x finer block-retirement granularity

    encode_kernel <<<blocksEnc, T>>>(pos);
    product_kernel<<<blocksM, T>>>(enc,  ptrs0, bufA);
    sum_kernel    <<<blocksM, T>>>(bufA, ptrs1, bufB);
    product_kernel<<<blocksM, T>>>(bufB, ptrs2, bufA);
    sum_kernel    <<<blocksM, T>>>(bufA, ptrs3, out);
}